// round 1
// baseline (speedup 1.0000x reference)
#include <cuda_runtime.h>
#include <math.h>

// ---------------- problem constants ----------------
#define MROWS  256
#define INF_   768
#define SHORTN 2000
#define NHEAD  2003   // SHORT + 3 cluster roots
#define LTGT   20

// cluster params
// lows:  2000, 12000, 40000, 100000
// OSZ:   10000, 28000, 60000
// HSZ:   384, 192, 96
// hidden offsets in g_h: 0, 256*384=98304, 98304+256*192=147456

// ---------------- device scratch (static, no allocs) ----------------
__device__ float g_h[MROWS * 672];          // hidden activations, 3 clusters packed
__device__ float g_hl[MROWS * NHEAD];       // head logits
__device__ float g_rowAcc[MROWS];           // per-row loss accumulator
__device__ float g_num[MROWS];              // per-row num_loss
__device__ float g_active[MROWS * 3];
__device__ float g_root[MROWS * 3];
__device__ int   g_uniq[MROWS * LTGT];

// ---------------- init: active flags, num_loss, uniq targets, zero acc ----------------
__global__ void init_kernel(const int* __restrict__ tgt) {
    int b = blockIdx.x;
    int lane = threadIdx.x;
    int t = (lane < LTGT) ? tgt[b * LTGT + lane] : -1;

    // unique-by-value within row (first occurrence wins)
    int uniq = (lane < LTGT) ? 1 : 0;
    #pragma unroll
    for (int j = 0; j < LTGT; ++j) {
        int tj = __shfl_sync(0xffffffffu, t, j);
        if (j < lane && tj == t) uniq = 0;
    }
    if (lane < LTGT) g_uniq[b * LTGT + lane] = uniq;

    const int lows[4] = {2000, 12000, 40000, 100000};
    float num = (float)SHORTN;
    #pragma unroll
    for (int i = 0; i < 3; ++i) {
        bool in = (lane < LTGT) && (t >= lows[i]) && (t < lows[i + 1]);
        unsigned ball = __ballot_sync(0xffffffffu, in);
        float a = ball ? 1.f : 0.f;
        if (lane == 0) g_active[b * 3 + i] = a;
        float csz = (float)(lows[i + 1] - lows[i]);
        num += (1.f - a) + a * csz;
    }
    if (lane == 0) {
        g_num[b] = num;
        g_rowAcc[b] = 0.f;
    }
}

// ---------------- tiled GEMM with fused epilogues ----------------
// C[m,n] = sum_k A[m,k] * W[n,k]   (A: [256,K] row-major, W: [N,K] row-major)
// EPI==0: store C               (hidden pre-LN)
// EPI==1: store C + accumulate softplus(C) into rowAcc   (head)
// EPI==2: accumulate -max(log1p(-root*sigmoid(C)), -100) * active into rowAcc (tail)
#define BM 64
#define BN 64
#define BK 16

template <int EPI>
__global__ void gemm_kernel(const float* __restrict__ A,
                            const float* __restrict__ W,
                            int N, int K,
                            float* __restrict__ C, int ldc,
                            int cluster) {
    __shared__ float As[BM][BK + 1];
    __shared__ float Bs[BN][BK + 1];
    __shared__ float sRow[BM];

    int tid = threadIdx.x;                 // 256 threads
    int tx = tid & 15, ty = tid >> 4;
    int bm0 = blockIdx.y * BM;
    int bn0 = blockIdx.x * BN;
    int lrow = tid >> 2;                   // 0..63
    int kq = (tid & 3) * 4;                // 0,4,8,12

    float c[4][4] = {};

    for (int k0 = 0; k0 < K; k0 += BK) {
        // load A tile (rows always valid: M==256)
        float4 av = *reinterpret_cast<const float4*>(&A[(size_t)(bm0 + lrow) * K + k0 + kq]);
        As[lrow][kq + 0] = av.x; As[lrow][kq + 1] = av.y;
        As[lrow][kq + 2] = av.z; As[lrow][kq + 3] = av.w;
        // load B tile (guard N)
        float4 bv = make_float4(0.f, 0.f, 0.f, 0.f);
        if (bn0 + lrow < N)
            bv = *reinterpret_cast<const float4*>(&W[(size_t)(bn0 + lrow) * K + k0 + kq]);
        Bs[lrow][kq + 0] = bv.x; Bs[lrow][kq + 1] = bv.y;
        Bs[lrow][kq + 2] = bv.z; Bs[lrow][kq + 3] = bv.w;
        __syncthreads();

        #pragma unroll
        for (int k = 0; k < BK; ++k) {
            float a[4], bb[4];
            #pragma unroll
            for (int i = 0; i < 4; ++i) a[i] = As[ty * 4 + i][k];
            #pragma unroll
            for (int j = 0; j < 4; ++j) bb[j] = Bs[tx * 4 + j][k];
            #pragma unroll
            for (int i = 0; i < 4; ++i)
                #pragma unroll
                for (int j = 0; j < 4; ++j)
                    c[i][j] += a[i] * bb[j];
        }
        __syncthreads();
    }

    if (EPI == 0) {
        #pragma unroll
        for (int i = 0; i < 4; ++i)
            #pragma unroll
            for (int j = 0; j < 4; ++j) {
                int n = bn0 + tx * 4 + j;
                if (n < N) C[(size_t)(bm0 + ty * 4 + i) * ldc + n] = c[i][j];
            }
        return;
    }

    float rsum[4] = {0.f, 0.f, 0.f, 0.f};
    float r[4];
    if (EPI == 2) {
        #pragma unroll
        for (int i = 0; i < 4; ++i)
            r[i] = g_root[(bm0 + ty * 4 + i) * 3 + cluster];
    }
    #pragma unroll
    for (int i = 0; i < 4; ++i) {
        #pragma unroll
        for (int j = 0; j < 4; ++j) {
            int n = bn0 + tx * 4 + j;
            if (n < N) {
                float l = c[i][j];
                if (EPI == 1) {
                    C[(size_t)(bm0 + ty * 4 + i) * ldc + n] = l;
                    rsum[i] += fmaxf(l, 0.f) + log1pf(__expf(-fabsf(l)));
                } else {
                    float s = 1.f / (1.f + __expf(-l));
                    float p = r[i] * s;
                    rsum[i] += -fmaxf(log1pf(-p), -100.f);
                }
            }
        }
    }

    if (tid < BM) sRow[tid] = 0.f;
    __syncthreads();
    #pragma unroll
    for (int i = 0; i < 4; ++i)
        atomicAdd(&sRow[ty * 4 + i], rsum[i]);
    __syncthreads();
    if (tid < BM) {
        float v = sRow[tid];
        if (EPI == 2) v *= g_active[(bm0 + tid) * 3 + cluster];
        atomicAdd(&g_rowAcc[bm0 + tid], v);
    }
}

// ---------------- LayerNorm + ReLU in place ----------------
__global__ void ln_kernel(float* __restrict__ h,
                          const float* __restrict__ p1,
                          const float* __restrict__ p2,
                          int H) {
    int b = blockIdx.x;
    float* row = h + (size_t)b * H;
    // disambiguate gamma (==1) vs beta (==0) robustly
    float v1 = p1[0], v2 = p2[0];
    const float* gp = (fabsf(v1 - 1.f) <= fabsf(v2 - 1.f)) ? p1 : p2;
    const float* bp = (gp == p1) ? p2 : p1;

    int tid = threadIdx.x;   // 128
    float s = 0.f, ss = 0.f;
    for (int k = tid; k < H; k += blockDim.x) {
        float v = row[k];
        s += v; ss += v * v;
    }
    #pragma unroll
    for (int o = 16; o; o >>= 1) {
        s  += __shfl_xor_sync(0xffffffffu, s, o);
        ss += __shfl_xor_sync(0xffffffffu, ss, o);
    }
    __shared__ float sh[10];
    int w = tid >> 5;
    if ((tid & 31) == 0) { sh[w] = s; sh[4 + w] = ss; }
    __syncthreads();
    if (tid == 0) {
        float S = sh[0] + sh[1] + sh[2] + sh[3];
        float SS = sh[4] + sh[5] + sh[6] + sh[7];
        sh[8] = S / (float)H;
        sh[9] = SS / (float)H;
    }
    __syncthreads();
    float mu = sh[8];
    float var = sh[9] - mu * mu;
    float inv = rsqrtf(var + 1e-5f);
    for (int k = tid; k < H; k += blockDim.x) {
        float v = (row[k] - mu) * inv * gp[k] + bp[k];
        row[k] = fmaxf(v, 0.f);
    }
}

// ---------------- fixup: target corrections + cluster-root terms ----------------
__global__ void fixup_kernel(const int* __restrict__ tgt,
                             const float* __restrict__ w2_0,
                             const float* __restrict__ w2_1,
                             const float* __restrict__ w2_2) {
    int b = blockIdx.x;
    int lane = threadIdx.x;   // 32
    int t  = (lane < LTGT) ? tgt[b * LTGT + lane] : -1;
    int uq = (lane < LTGT) ? g_uniq[b * LTGT + lane] : 0;

    float corr = 0.f;
    // head shortlist: bce(l,1) = softplus(l) - l -> subtract l at unique target cols
    if (uq && t >= 0 && t < SHORTN) corr -= g_hl[b * NHEAD + t];

    // cluster root columns: (1-active)*softplus(l); also store root sigmoid
    if (lane < 3) {
        float l = g_hl[b * NHEAD + SHORTN + lane];
        float a = g_active[b * 3 + lane];
        corr += (1.f - a) * (fmaxf(l, 0.f) + log1pf(__expf(-fabsf(l))));
        g_root[b * 3 + lane] = 1.f / (1.f + __expf(-l));
    }
    #pragma unroll
    for (int o = 16; o; o >>= 1) corr += __shfl_xor_sync(0xffffffffu, corr, o);

    __threadfence_block();
    __syncwarp();

    // tail corrections for y==1 positions:
    //   add -max(log(p),-100) + max(log1p(-p),-100)
    float tc = 0.f;
    for (int j = 0; j < LTGT; ++j) {
        int tj = __shfl_sync(0xffffffffu, t, j);
        int uj = __shfl_sync(0xffffffffu, uq, j);
        if (!uj || tj < SHORTN) continue;
        const float* w2; int H, hoff, low, ci;
        if (tj < 12000)      { w2 = w2_0; H = 384; hoff = 0;      low = 2000;  ci = 0; }
        else if (tj < 40000) { w2 = w2_1; H = 192; hoff = 98304;  low = 12000; ci = 1; }
        else                 { w2 = w2_2; H = 96;  hoff = 147456; low = 40000; ci = 2; }
        int col = tj - low;
        const float* hrow = g_h + hoff + (size_t)b * H;
        const float* wrow = w2 + (size_t)col * H;
        float part = 0.f;
        for (int k = lane; k < H; k += 32) part += hrow[k] * wrow[k];
        #pragma unroll
        for (int o = 16; o; o >>= 1) part += __shfl_xor_sync(0xffffffffu, part, o);
        if (lane == 0) {
            float r = g_root[b * 3 + ci];
            float s = 1.f / (1.f + __expf(-part));
            float p = r * s;
            tc += -fmaxf(logf(p), -100.f) + fmaxf(log1pf(-p), -100.f);
        }
    }
    if (lane == 0) g_rowAcc[b] += corr + tc;
}

// ---------------- finalize: mean(rowAcc / num) ----------------
__global__ void finalize_kernel(float* __restrict__ out) {
    int tid = threadIdx.x;   // 256
    float v = g_rowAcc[tid] / g_num[tid];
    #pragma unroll
    for (int o = 16; o; o >>= 1) v += __shfl_xor_sync(0xffffffffu, v, o);
    __shared__ float sh[8];
    if ((tid & 31) == 0) sh[tid >> 5] = v;
    __syncthreads();
    if (tid == 0) {
        float s = 0.f;
        #pragma unroll
        for (int i = 0; i < 8; ++i) s += sh[i];
        out[0] = s / 256.f;
    }
}

// ---------------- launch ----------------
extern "C" void kernel_launch(void* const* d_in, const int* in_sizes, int n_in,
                              void* d_out, int out_size) {
    const float* x = nullptr;
    const float* headW = nullptr;
    const int* tgt = nullptr;
    const float* w1[3] = {nullptr, nullptr, nullptr};
    const float* w2[3] = {nullptr, nullptr, nullptr};
    const float* gb_a[3] = {nullptr, nullptr, nullptr};  // first-seen of (g,b)
    const float* gb_b[3] = {nullptr, nullptr, nullptr};  // second-seen
    int gbcount[3] = {0, 0, 0};

    for (int i = 0; i < n_in; ++i) {
        int s = in_sizes[i];
        const float* p = (const float*)d_in[i];
        switch (s) {
            case 196608:  x = p; break;                       // 256*768
            case 1538304: headW = p; break;                   // 2003*768
            case 5120:    tgt = (const int*)d_in[i]; break;   // 256*20
            case 294912:  w1[0] = p; break;                   // 384*768
            case 147456:  w1[1] = p; break;                   // 192*768
            case 73728:   w1[2] = p; break;                   // 96*768
            case 3840000: w2[0] = p; break;                   // 10000*384
            case 5376000: w2[1] = p; break;                   // 28000*192
            case 5760000: w2[2] = p; break;                   // 60000*96
            case 384: if (gbcount[0]++ == 0) gb_a[0] = p; else gb_b[0] = p; break;
            case 192: if (gbcount[1]++ == 0) gb_a[1] = p; else gb_b[1] = p; break;
            case 96:  if (gbcount[2]++ == 0) gb_a[2] = p; else gb_b[2] = p; break;
            default: break;
        }
    }

    void* hp;  cudaGetSymbolAddress(&hp,  g_h);
    void* hlp; cudaGetSymbolAddress(&hlp, g_hl);
    float* h  = (float*)hp;
    float* hl = (float*)hlp;

    const int HSZ[3]  = {384, 192, 96};
    const int OSZ[3]  = {10000, 28000, 60000};
    const int HOFF[3] = {0, 98304, 147456};

    // 0) init
    init_kernel<<<MROWS, 32>>>(tgt);

    // 1) hidden GEMMs (store raw)
    for (int i = 0; i < 3; ++i) {
        dim3 grid((HSZ[i] + BN - 1) / BN, MROWS / BM);
        gemm_kernel<0><<<grid, 256>>>(x, w1[i], HSZ[i], INF_, h + HOFF[i], HSZ[i], 0);
    }

    // 2) LayerNorm + ReLU
    for (int i = 0; i < 3; ++i)
        ln_kernel<<<MROWS, 128>>>(h + HOFF[i], gb_a[i], gb_b[i], HSZ[i]);

    // 3) head GEMM (store logits + softplus accumulate)
    {
        dim3 grid((NHEAD + BN - 1) / BN, MROWS / BM);
        gemm_kernel<1><<<grid, 256>>>(x, headW, NHEAD, INF_, hl, NHEAD, 0);
    }

    // 4) fixups (needs head logits + hidden; produces roots)
    fixup_kernel<<<MROWS, 32>>>(tgt, w2[0], w2[1], w2[2]);

    // 5) tail GEMMs with fused BCE epilogue
    for (int i = 0; i < 3; ++i) {
        dim3 grid((OSZ[i] + BN - 1) / BN, MROWS / BM);
        gemm_kernel<2><<<grid, 256>>>(h + HOFF[i], w2[i], OSZ[i], HSZ[i], nullptr, 0, i);
    }

    // 6) finalize
    finalize_kernel<<<1, 256>>>((float*)d_out);
}

// round 2
// speedup vs baseline: 1.0578x; 1.0578x over previous
#include <cuda_runtime.h>
#include <math.h>

// ---------------- problem constants ----------------
#define MROWS  256
#define INF_   768
#define SHORTN 2000
#define NHEAD  2003   // SHORT + 3 cluster roots
#define LTGT   20

// cluster params
// lows:  2000, 12000, 40000, 100000
// OSZ:   10000, 28000, 60000
// HSZ:   384, 192, 96
// hidden offsets in g_h: 0, 256*384=98304, 98304+256*192=147456

// ---------------- device scratch (static, no allocs) ----------------
__device__ float g_h[MROWS * 672];          // hidden activations, 3 clusters packed
__device__ float g_hl[MROWS * NHEAD];       // head logits
__device__ float g_rowAcc[MROWS];           // per-row loss accumulator
__device__ float g_num[MROWS];              // per-row num_loss
__device__ float g_active[MROWS * 3];
__device__ float g_root[MROWS * 3];
__device__ int   g_uniq[MROWS * LTGT];

// ---------------- init: active flags, num_loss, uniq targets, zero acc ----------------
__global__ void init_kernel(const int* __restrict__ tgt) {
    int b = blockIdx.x;
    int lane = threadIdx.x;
    int t = (lane < LTGT) ? tgt[b * LTGT + lane] : -1;

    // unique-by-value within row (first occurrence wins)
    int uniq = (lane < LTGT) ? 1 : 0;
    #pragma unroll
    for (int j = 0; j < LTGT; ++j) {
        int tj = __shfl_sync(0xffffffffu, t, j);
        if (j < lane && tj == t) uniq = 0;
    }
    if (lane < LTGT) g_uniq[b * LTGT + lane] = uniq;

    const int lows[4] = {2000, 12000, 40000, 100000};
    float num = (float)SHORTN;
    #pragma unroll
    for (int i = 0; i < 3; ++i) {
        bool in = (lane < LTGT) && (t >= lows[i]) && (t < lows[i + 1]);
        unsigned ball = __ballot_sync(0xffffffffu, in);
        float a = ball ? 1.f : 0.f;
        if (lane == 0) g_active[b * 3 + i] = a;
        float csz = (float)(lows[i + 1] - lows[i]);
        num += (1.f - a) + a * csz;
    }
    if (lane == 0) {
        g_num[b] = num;
        g_rowAcc[b] = 0.f;
    }
}

// ---------------- tiled GEMM with fused epilogues ----------------
// C[m,n] = sum_k A[m,k] * W[n,k]   (A: [256,K] row-major, W: [N,K] row-major)
// EPI==0: store C               (hidden pre-LN)
// EPI==1: store C + accumulate softplus(C) into rowAcc   (head)
// EPI==2: accumulate -max(log1p(-root*sigmoid(C)), -100) * active into rowAcc (tail)
#define BM 64
#define BN 64
#define BK 16

template <int EPI>
__global__ void gemm_kernel(const float* __restrict__ A,
                            const float* __restrict__ W,
                            int N, int K,
                            float* __restrict__ C, int ldc,
                            int cluster) {
    __shared__ float As[BM][BK + 1];
    __shared__ float Bs[BN][BK + 1];
    __shared__ float sRow[BM];

    int tid = threadIdx.x;                 // 256 threads
    int tx = tid & 15, ty = tid >> 4;
    int bm0 = blockIdx.y * BM;
    int bn0 = blockIdx.x * BN;
    int lrow = tid >> 2;                   // 0..63
    int kq = (tid & 3) * 4;                // 0,4,8,12

    float c[4][4] = {};

    for (int k0 = 0; k0 < K; k0 += BK) {
        // load A tile (rows always valid: M==256)
        float4 av = *reinterpret_cast<const float4*>(&A[(size_t)(bm0 + lrow) * K + k0 + kq]);
        As[lrow][kq + 0] = av.x; As[lrow][kq + 1] = av.y;
        As[lrow][kq + 2] = av.z; As[lrow][kq + 3] = av.w;
        // load B tile (guard N)
        float4 bv = make_float4(0.f, 0.f, 0.f, 0.f);
        if (bn0 + lrow < N)
            bv = *reinterpret_cast<const float4*>(&W[(size_t)(bn0 + lrow) * K + k0 + kq]);
        Bs[lrow][kq + 0] = bv.x; Bs[lrow][kq + 1] = bv.y;
        Bs[lrow][kq + 2] = bv.z; Bs[lrow][kq + 3] = bv.w;
        __syncthreads();

        #pragma unroll
        for (int k = 0; k < BK; ++k) {
            float a[4], bb[4];
            #pragma unroll
            for (int i = 0; i < 4; ++i) a[i] = As[ty * 4 + i][k];
            #pragma unroll
            for (int j = 0; j < 4; ++j) bb[j] = Bs[tx * 4 + j][k];
            #pragma unroll
            for (int i = 0; i < 4; ++i)
                #pragma unroll
                for (int j = 0; j < 4; ++j)
                    c[i][j] += a[i] * bb[j];
        }
        __syncthreads();
    }

    if (EPI == 0) {
        #pragma unroll
        for (int i = 0; i < 4; ++i)
            #pragma unroll
            for (int j = 0; j < 4; ++j) {
                int n = bn0 + tx * 4 + j;
                if (n < N) C[(size_t)(bm0 + ty * 4 + i) * ldc + n] = c[i][j];
            }
        return;
    }

    float rsum[4] = {0.f, 0.f, 0.f, 0.f};
    float r[4];
    if (EPI == 2) {
        #pragma unroll
        for (int i = 0; i < 4; ++i)
            r[i] = g_root[(bm0 + ty * 4 + i) * 3 + cluster];
    }
    #pragma unroll
    for (int i = 0; i < 4; ++i) {
        #pragma unroll
        for (int j = 0; j < 4; ++j) {
            int n = bn0 + tx * 4 + j;
            if (n < N) {
                float l = c[i][j];
                if (EPI == 1) {
                    C[(size_t)(bm0 + ty * 4 + i) * ldc + n] = l;
                    rsum[i] += fmaxf(l, 0.f) + log1pf(__expf(-fabsf(l)));
                } else {
                    float s = 1.f / (1.f + __expf(-l));
                    float p = r[i] * s;
                    rsum[i] += -fmaxf(log1pf(-p), -100.f);
                }
            }
        }
    }

    if (tid < BM) sRow[tid] = 0.f;
    __syncthreads();
    #pragma unroll
    for (int i = 0; i < 4; ++i)
        atomicAdd(&sRow[ty * 4 + i], rsum[i]);
    __syncthreads();
    if (tid < BM) {
        float v = sRow[tid];
        if (EPI == 2) v *= g_active[(bm0 + tid) * 3 + cluster];
        atomicAdd(&g_rowAcc[bm0 + tid], v);
    }
}

// ---------------- LayerNorm + ReLU in place ----------------
__global__ void ln_kernel(float* __restrict__ h,
                          const float* __restrict__ p1,
                          const float* __restrict__ p2,
                          int H) {
    int b = blockIdx.x;
    float* row = h + (size_t)b * H;
    // disambiguate gamma (==1) vs beta (==0) robustly
    float v1 = p1[0], v2 = p2[0];
    const float* gp = (fabsf(v1 - 1.f) <= fabsf(v2 - 1.f)) ? p1 : p2;
    const float* bp = (gp == p1) ? p2 : p1;

    int tid = threadIdx.x;   // 128
    float s = 0.f, ss = 0.f;
    for (int k = tid; k < H; k += blockDim.x) {
        float v = row[k];
        s += v; ss += v * v;
    }
    #pragma unroll
    for (int o = 16; o; o >>= 1) {
        s  += __shfl_xor_sync(0xffffffffu, s, o);
        ss += __shfl_xor_sync(0xffffffffu, ss, o);
    }
    __shared__ float sh[10];
    int w = tid >> 5;
    if ((tid & 31) == 0) { sh[w] = s; sh[4 + w] = ss; }
    __syncthreads();
    if (tid == 0) {
        float S = sh[0] + sh[1] + sh[2] + sh[3];
        float SS = sh[4] + sh[5] + sh[6] + sh[7];
        sh[8] = S / (float)H;
        sh[9] = SS / (float)H;
    }
    __syncthreads();
    float mu = sh[8];
    float var = sh[9] - mu * mu;
    float inv = rsqrtf(var + 1e-5f);
    for (int k = tid; k < H; k += blockDim.x) {
        float v = (row[k] - mu) * inv * gp[k] + bp[k];
        row[k] = fmaxf(v, 0.f);
    }
}

// ---------------- fixup: target corrections + cluster-root terms ----------------
__global__ void fixup_kernel(const int* __restrict__ tgt,
                             const float* __restrict__ w2_0,
                             const float* __restrict__ w2_1,
                             const float* __restrict__ w2_2) {
    int b = blockIdx.x;
    int lane = threadIdx.x;   // 32
    int t  = (lane < LTGT) ? tgt[b * LTGT + lane] : -1;
    int uq = (lane < LTGT) ? g_uniq[b * LTGT + lane] : 0;

    float corr = 0.f;
    // head shortlist: bce(l,1) = softplus(l) - l -> subtract l at unique target cols
    if (uq && t >= 0 && t < SHORTN) corr -= g_hl[b * NHEAD + t];

    // cluster root columns: (1-active)*softplus(l); also store root sigmoid
    if (lane < 3) {
        float l = g_hl[b * NHEAD + SHORTN + lane];
        float a = g_active[b * 3 + lane];
        corr += (1.f - a) * (fmaxf(l, 0.f) + log1pf(__expf(-fabsf(l))));
        g_root[b * 3 + lane] = 1.f / (1.f + __expf(-l));
    }
    #pragma unroll
    for (int o = 16; o; o >>= 1) corr += __shfl_xor_sync(0xffffffffu, corr, o);

    __threadfence_block();
    __syncwarp();

    // tail corrections for y==1 positions:
    //   add -max(log(p),-100) + max(log1p(-p),-100)
    float tc = 0.f;
    for (int j = 0; j < LTGT; ++j) {
        int tj = __shfl_sync(0xffffffffu, t, j);
        int uj = __shfl_sync(0xffffffffu, uq, j);
        if (!uj || tj < SHORTN) continue;
        const float* w2; int H, hoff, low, ci;
        if (tj < 12000)      { w2 = w2_0; H = 384; hoff = 0;      low = 2000;  ci = 0; }
        else if (tj < 40000) { w2 = w2_1; H = 192; hoff = 98304;  low = 12000; ci = 1; }
        else                 { w2 = w2_2; H = 96;  hoff = 147456; low = 40000; ci = 2; }
        int col = tj - low;
        const float* hrow = g_h + hoff + (size_t)b * H;
        const float* wrow = w2 + (size_t)col * H;
        float part = 0.f;
        for (int k = lane; k < H; k += 32) part += hrow[k] * wrow[k];
        #pragma unroll
        for (int o = 16; o; o >>= 1) part += __shfl_xor_sync(0xffffffffu, part, o);
        if (lane == 0) {
            float r = g_root[b * 3 + ci];
            float s = 1.f / (1.f + __expf(-part));
            float p = r * s;
            tc += -fmaxf(logf(p), -100.f) + fmaxf(log1pf(-p), -100.f);
        }
    }
    if (lane == 0) g_rowAcc[b] += corr + tc;
}

// ---------------- finalize: mean(rowAcc / num) ----------------
__global__ void finalize_kernel(float* __restrict__ out) {
    int tid = threadIdx.x;   // 256
    float v = g_rowAcc[tid] / g_num[tid];
    #pragma unroll
    for (int o = 16; o; o >>= 1) v += __shfl_xor_sync(0xffffffffu, v, o);
    __shared__ float sh[8];
    if ((tid & 31) == 0) sh[tid >> 5] = v;
    __syncthreads();
    if (tid == 0) {
        float s = 0.f;
        #pragma unroll
        for (int i = 0; i < 8; ++i) s += sh[i];
        out[0] = s / 256.f;
    }
}

// ---------------- launch ----------------
extern "C" void kernel_launch(void* const* d_in, const int* in_sizes, int n_in,
                              void* d_out, int out_size) {
    const float* x = nullptr;
    const float* headW = nullptr;
    const int* tgt = nullptr;
    const float* w1[3] = {nullptr, nullptr, nullptr};
    const float* w2[3] = {nullptr, nullptr, nullptr};
    const float* gb_a[3] = {nullptr, nullptr, nullptr};  // first-seen of (g,b)
    const float* gb_b[3] = {nullptr, nullptr, nullptr};  // second-seen
    int gbcount[3] = {0, 0, 0};

    for (int i = 0; i < n_in; ++i) {
        int s = in_sizes[i];
        const float* p = (const float*)d_in[i];
        switch (s) {
            case 196608:  x = p; break;                       // 256*768
            case 1538304: headW = p; break;                   // 2003*768
            case 5120:    tgt = (const int*)d_in[i]; break;   // 256*20
            case 294912:  w1[0] = p; break;                   // 384*768
            case 147456:  w1[1] = p; break;                   // 192*768
            case 73728:   w1[2] = p; break;                   // 96*768
            case 3840000: w2[0] = p; break;                   // 10000*384
            case 5376000: w2[1] = p; break;                   // 28000*192
            case 5760000: w2[2] = p; break;                   // 60000*96
            case 384: if (gbcount[0]++ == 0) gb_a[0] = p; else gb_b[0] = p; break;
            case 192: if (gbcount[1]++ == 0) gb_a[1] = p; else gb_b[1] = p; break;
            case 96:  if (gbcount[2]++ == 0) gb_a[2] = p; else gb_b[2] = p; break;
            default: break;
        }
    }

    void* hp;  cudaGetSymbolAddress(&hp,  g_h);
    void* hlp; cudaGetSymbolAddress(&hlp, g_hl);
    float* h  = (float*)hp;
    float* hl = (float*)hlp;

    const int HSZ[3]  = {384, 192, 96};
    const int OSZ[3]  = {10000, 28000, 60000};
    const int HOFF[3] = {0, 98304, 147456};

    // 0) init
    init_kernel<<<MROWS, 32>>>(tgt);

    // 1) hidden GEMMs (store raw)
    for (int i = 0; i < 3; ++i) {
        dim3 grid((HSZ[i] + BN - 1) / BN, MROWS / BM);
        gemm_kernel<0><<<grid, 256>>>(x, w1[i], HSZ[i], INF_, h + HOFF[i], HSZ[i], 0);
    }

    // 2) LayerNorm + ReLU
    for (int i = 0; i < 3; ++i)
        ln_kernel<<<MROWS, 128>>>(h + HOFF[i], gb_a[i], gb_b[i], HSZ[i]);

    // 3) head GEMM (store logits + softplus accumulate)
    {
        dim3 grid((NHEAD + BN - 1) / BN, MROWS / BM);
        gemm_kernel<1><<<grid, 256>>>(x, headW, NHEAD, INF_, hl, NHEAD, 0);
    }

    // 4) fixups (needs head logits + hidden; produces roots)
    fixup_kernel<<<MROWS, 32>>>(tgt, w2[0], w2[1], w2[2]);

    // 5) tail GEMMs with fused BCE epilogue
    for (int i = 0; i < 3; ++i) {
        dim3 grid((OSZ[i] + BN - 1) / BN, MROWS / BM);
        gemm_kernel<2><<<grid, 256>>>(h + HOFF[i], w2[i], OSZ[i], HSZ[i], nullptr, 0, i);
    }

    // 6) finalize
    finalize_kernel<<<1, 256>>>((float*)d_out);
}

// round 4
// speedup vs baseline: 3.8958x; 3.6830x over previous
#include <cuda_runtime.h>
#include <cuda_bf16.h>
#include <math.h>
#include <stdint.h>

#define MROWS  256
#define INF_   768
#define SHORTN 2000
#define NHEAD  2003
#define LTGT   20

// clusters: lows 2000,12000,40000,100000; OSZ 10000,28000,60000; HSZ 384,192,96
// hidden pack offsets (elements): 0, 98304, 147456

// ---------------- device scratch ----------------
__device__ __align__(16) __nv_bfloat16 g_xb[MROWS * INF_];
__device__ __align__(16) float          g_h[MROWS * 672];
__device__ __align__(16) __nv_bfloat16 g_hb[MROWS * 672];
__device__ __align__(16) float          g_hl[MROWS * NHEAD];
__device__ float g_rowAcc[MROWS];
__device__ float g_num[MROWS];
__device__ float g_active[MROWS * 3];
__device__ float g_root[MROWS * 3];
__device__ int   g_uniq[MROWS * LTGT];

__device__ __forceinline__ uint32_t smem_u32(const void* p) {
    uint32_t a;
    asm("{ .reg .u64 t; cvta.to.shared.u64 t, %1; cvt.u32.u64 %0, t; }" : "=r"(a) : "l"(p));
    return a;
}

#define LDSM_X4(d0, d1, d2, d3, addr) \
    asm volatile("ldmatrix.sync.aligned.m8n8.x4.shared.b16 {%0,%1,%2,%3}, [%4];" \
        : "=r"(d0), "=r"(d1), "=r"(d2), "=r"(d3) : "r"(addr))

#define MMA16816(c, a, b) \
    asm volatile("mma.sync.aligned.m16n8k16.row.col.f32.bf16.bf16.f32 " \
        "{%0,%1,%2,%3},{%4,%5,%6,%7},{%8,%9},{%0,%1,%2,%3};" \
        : "+f"((c)[0]), "+f"((c)[1]), "+f"((c)[2]), "+f"((c)[3]) \
        : "r"((a)[0]), "r"((a)[1]), "r"((a)[2]), "r"((a)[3]), "r"((b)[0]), "r"((b)[1]))

// ---------------- warp-MMA mainloop ----------------
// c[2][8][4] += A[bm0:+128, 0:K](bf16, ldA) @ W[nloc:+nval, 0:K](fp32)^T
// smA/smB: 128 rows x 64 bf16, 128B rows, 16B-chunk XOR swizzle.
__device__ __forceinline__ void mma_loop(
    const __nv_bfloat16* __restrict__ A, int ldA, int bm0,
    const float* __restrict__ W, int nloc, int nval, int K,
    __nv_bfloat16* smA, __nv_bfloat16* smB, float c[2][8][4])
{
    int tid = threadIdx.x;
    int lane = tid & 31, wid = tid >> 5;
    int wm = wid & 3, wn = wid >> 2;
    int lo3 = lane & 7, gg1 = (lane >> 3) & 1, gg2 = (lane >> 4) & 1;
    uint32_t smAu = smem_u32(smA), smBu = smem_u32(smB);

    int nchunk = (K + 63) >> 6;
    for (int ch = 0; ch < nchunk; ++ch) {
        int kbase = ch << 6;
        int kreal = K - kbase; if (kreal > 64) kreal = 64;
        __syncthreads();

        #pragma unroll
        for (int it = 0; it < 4; ++it) {
            int idx = tid + it * 256;
            int r = idx >> 3, kc = idx & 7;
            if (kc * 8 < kreal) {
                uint4 v = *reinterpret_cast<const uint4*>(
                    A + (size_t)(bm0 + r) * ldA + kbase + kc * 8);
                *reinterpret_cast<uint4*>(
                    reinterpret_cast<char*>(smA) + r * 128 + ((kc ^ (r & 7)) << 4)) = v;
            }
        }
        #pragma unroll
        for (int it = 0; it < 4; ++it) {
            int idx = tid + it * 256;
            int r = idx >> 3, kc = idx & 7;
            if (kc * 8 < kreal) {
                uint4 o = make_uint4(0u, 0u, 0u, 0u);
                if (r < nval) {
                    const float* s = W + (size_t)(nloc + r) * K + kbase + kc * 8;
                    float4 v0 = *reinterpret_cast<const float4*>(s);
                    float4 v1 = *reinterpret_cast<const float4*>(s + 4);
                    asm("cvt.rn.bf16x2.f32 %0, %1, %2;" : "=r"(o.x) : "f"(v0.y), "f"(v0.x));
                    asm("cvt.rn.bf16x2.f32 %0, %1, %2;" : "=r"(o.y) : "f"(v0.w), "f"(v0.z));
                    asm("cvt.rn.bf16x2.f32 %0, %1, %2;" : "=r"(o.z) : "f"(v1.y), "f"(v1.x));
                    asm("cvt.rn.bf16x2.f32 %0, %1, %2;" : "=r"(o.w) : "f"(v1.w), "f"(v1.z));
                }
                *reinterpret_cast<uint4*>(
                    reinterpret_cast<char*>(smB) + r * 128 + ((kc ^ (r & 7)) << 4)) = o;
            }
        }
        __syncthreads();

        int ks = kreal >> 4;
        for (int s = 0; s < ks; ++s) {
            uint32_t a[2][4];
            #pragma unroll
            for (int t = 0; t < 2; ++t) {
                int row = wm * 32 + t * 16 + gg1 * 8 + lo3;
                uint32_t ad = smAu + row * 128 + (((2 * s + gg2) ^ (row & 7)) << 4);
                LDSM_X4(a[t][0], a[t][1], a[t][2], a[t][3], ad);
            }
            uint32_t b[8][2];
            #pragma unroll
            for (int p = 0; p < 4; ++p) {
                int row = wn * 64 + p * 16 + gg2 * 8 + lo3;
                uint32_t bd = smBu + row * 128 + (((2 * s + gg1) ^ (row & 7)) << 4);
                LDSM_X4(b[2 * p][0], b[2 * p][1], b[2 * p + 1][0], b[2 * p + 1][1], bd);
            }
            #pragma unroll
            for (int t = 0; t < 2; ++t)
                #pragma unroll
                for (int n = 0; n < 8; ++n)
                    MMA16816(c[t][n], a[t], b[n]);
        }
    }
    __syncthreads();
}

// ---------------- prep: x -> bf16, per-row init ----------------
__global__ void prep_kernel(const float* __restrict__ x, const int* __restrict__ tgt) {
    int b = blockIdx.x;
    int tid = threadIdx.x;
    for (int k = tid; k < INF_; k += 256)
        g_xb[b * INF_ + k] = __float2bfloat16(x[(size_t)b * INF_ + k]);

    if (tid < 32) {
        int lane = tid;
        int t = (lane < LTGT) ? tgt[b * LTGT + lane] : -1;
        int uniq = (lane < LTGT) ? 1 : 0;
        #pragma unroll
        for (int j = 0; j < LTGT; ++j) {
            int tj = __shfl_sync(0xffffffffu, t, j);
            if (j < lane && tj == t) uniq = 0;
        }
        if (lane < LTGT) g_uniq[b * LTGT + lane] = uniq;

        const int lows[4] = {2000, 12000, 40000, 100000};
        float num = (float)SHORTN;
        #pragma unroll
        for (int i = 0; i < 3; ++i) {
            bool in = (lane < LTGT) && (t >= lows[i]) && (t < lows[i + 1]);
            unsigned ball = __ballot_sync(0xffffffffu, in);
            float a = ball ? 1.f : 0.f;
            if (lane == 0) g_active[b * 3 + i] = a;
            num += (1.f - a) + a * (float)(lows[i + 1] - lows[i]);
        }
        if (lane == 0) { g_num[b] = num; g_rowAcc[b] = 0.f; }
    }
}

// ---------------- mm1: head + hidden GEMMs ----------------
__global__ void __launch_bounds__(256) mm1_kernel(const float* __restrict__ headW,
                                                  const float* __restrict__ w1_0,
                                                  const float* __restrict__ w1_1,
                                                  const float* __restrict__ w1_2) {
    __shared__ __align__(16) __nv_bfloat16 smA[128 * 64];
    __shared__ __align__(16) __nv_bfloat16 smB[128 * 64];

    int t = blockIdx.x;
    int bm0 = blockIdx.y * 128;
    const float* W; float* outF; int ldc, nloc, nval, mode;
    if (t < 16)      { W = headW; outF = g_hl;         ldc = NHEAD; nloc = t << 7;        nval = NHEAD - nloc; if (nval > 128) nval = 128; mode = 1; }
    else if (t < 19) { W = w1_0;  outF = g_h;          ldc = 384;   nloc = (t - 16) << 7; nval = 128; mode = 0; }
    else if (t < 21) { W = w1_1;  outF = g_h + 98304;  ldc = 192;   nloc = (t - 19) << 7; nval = 192 - nloc; if (nval > 128) nval = 128; mode = 0; }
    else             { W = w1_2;  outF = g_h + 147456; ldc = 96;    nloc = 0;             nval = 96;  mode = 0; }

    float c[2][8][4] = {};
    mma_loop(g_xb, INF_, bm0, W, nloc, nval, INF_, smA, smB, c);

    int tid = threadIdx.x;
    int lane = tid & 31, wid = tid >> 5;
    int wm = wid & 3, wn = wid >> 2;
    float* sRow = reinterpret_cast<float*>(smA);
    if (mode == 1) { if (tid < 128) sRow[tid] = 0.f; }
    __syncthreads();

    float rs[2][2] = {{0.f, 0.f}, {0.f, 0.f}};
    #pragma unroll
    for (int tt = 0; tt < 2; ++tt) {
        int r0 = bm0 + wm * 32 + tt * 16 + (lane >> 2);
        #pragma unroll
        for (int n = 0; n < 8; ++n) {
            int col = wn * 64 + n * 8 + (lane & 3) * 2;
            #pragma unroll
            for (int q = 0; q < 2; ++q) {
                if (col + q < nval) {
                    float l0 = c[tt][n][q];
                    float l1 = c[tt][n][2 + q];
                    outF[(size_t)r0 * ldc + nloc + col + q] = l0;
                    outF[(size_t)(r0 + 8) * ldc + nloc + col + q] = l1;
                    if (mode == 1) {
                        rs[tt][0] += fmaxf(l0, 0.f) + log1pf(__expf(-fabsf(l0)));
                        rs[tt][1] += fmaxf(l1, 0.f) + log1pf(__expf(-fabsf(l1)));
                    }
                }
            }
        }
    }
    if (mode == 1) {
        #pragma unroll
        for (int tt = 0; tt < 2; ++tt) {
            int lr = wm * 32 + tt * 16 + (lane >> 2);
            atomicAdd(&sRow[lr], rs[tt][0]);
            atomicAdd(&sRow[lr + 8], rs[tt][1]);
        }
        __syncthreads();
        if (tid < 128) atomicAdd(&g_rowAcc[bm0 + tid], sRow[tid]);
    }
}

// ---------------- LayerNorm + ReLU (fp32 + bf16 out) ----------------
__global__ void ln_kernel(const float* __restrict__ p1a, const float* __restrict__ p2a,
                          const float* __restrict__ p1b, const float* __restrict__ p2b,
                          const float* __restrict__ p1c, const float* __restrict__ p2c) {
    int ci = blockIdx.y;
    int b = blockIdx.x;
    int H, hoff; const float* p1; const float* p2;
    if (ci == 0)      { H = 384; hoff = 0;      p1 = p1a; p2 = p2a; }
    else if (ci == 1) { H = 192; hoff = 98304;  p1 = p1b; p2 = p2b; }
    else              { H = 96;  hoff = 147456; p1 = p1c; p2 = p2c; }
    float* row = g_h + hoff + (size_t)b * H;
    __nv_bfloat16* rowb = g_hb + hoff + (size_t)b * H;

    float v1 = p1[0], v2 = p2[0];
    const float* gp = (fabsf(v1 - 1.f) <= fabsf(v2 - 1.f)) ? p1 : p2;
    const float* bp = (gp == p1) ? p2 : p1;

    int tid = threadIdx.x;   // 128
    float s = 0.f, ss = 0.f;
    for (int k = tid; k < H; k += 128) {
        float v = row[k];
        s += v; ss += v * v;
    }
    #pragma unroll
    for (int o = 16; o; o >>= 1) {
        s  += __shfl_xor_sync(0xffffffffu, s, o);
        ss += __shfl_xor_sync(0xffffffffu, ss, o);
    }
    __shared__ float sh[10];
    int w = tid >> 5;
    if ((tid & 31) == 0) { sh[w] = s; sh[4 + w] = ss; }
    __syncthreads();
    if (tid == 0) {
        float S = sh[0] + sh[1] + sh[2] + sh[3];
        float SS = sh[4] + sh[5] + sh[6] + sh[7];
        sh[8] = S / (float)H;
        sh[9] = SS / (float)H;
    }
    __syncthreads();
    float mu = sh[8];
    float inv = rsqrtf(sh[9] - mu * mu + 1e-5f);
    for (int k = tid; k < H; k += 128) {
        float v = fmaxf((row[k] - mu) * inv * gp[k] + bp[k], 0.f);
        row[k] = v;
        rowb[k] = __float2bfloat16(v);
    }
}

// ---------------- fixup ----------------
__global__ void fixup_kernel(const int* __restrict__ tgt,
                             const float* __restrict__ w2_0,
                             const float* __restrict__ w2_1,
                             const float* __restrict__ w2_2) {
    int b = blockIdx.x;
    int lane = threadIdx.x;   // 32
    int t  = (lane < LTGT) ? tgt[b * LTGT + lane] : -1;
    int uq = (lane < LTGT) ? g_uniq[b * LTGT + lane] : 0;

    float corr = 0.f;
    if (uq && t >= 0 && t < SHORTN) corr -= g_hl[b * NHEAD + t];

    // epilogue added softplus(l) unconditionally; reference term is (1-a)*softplus(l)
    if (lane < 3) {
        float l = g_hl[b * NHEAD + SHORTN + lane];
        float a = g_active[b * 3 + lane];
        corr += -a * (fmaxf(l, 0.f) + log1pf(__expf(-fabsf(l))));
        g_root[b * 3 + lane] = 1.f / (1.f + __expf(-l));
    }
    #pragma unroll
    for (int o = 16; o; o >>= 1) corr += __shfl_xor_sync(0xffffffffu, corr, o);

    __threadfence_block();
    __syncwarp();

    float tc = 0.f;
    for (int j = 0; j < LTGT; ++j) {
        int tj = __shfl_sync(0xffffffffu, t, j);
        int uj = __shfl_sync(0xffffffffu, uq, j);
        if (!uj || tj < SHORTN) continue;
        const float* w2; int H, hoff, low, ci;
        if (tj < 12000)      { w2 = w2_0; H = 384; hoff = 0;      low = 2000;  ci = 0; }
        else if (tj < 40000) { w2 = w2_1; H = 192; hoff = 98304;  low = 12000; ci = 1; }
        else                 { w2 = w2_2; H = 96;  hoff = 147456; low = 40000; ci = 2; }
        int col = tj - low;
        const float* hrow = g_h + hoff + (size_t)b * H;
        const float* wrow = w2 + (size_t)col * H;
        float part = 0.f;
        for (int k = lane; k < H; k += 32) part += hrow[k] * wrow[k];
        #pragma unroll
        for (int o = 16; o; o >>= 1) part += __shfl_xor_sync(0xffffffffu, part, o);
        if (lane == 0) {
            float r = g_root[b * 3 + ci];
            float s = 1.f / (1.f + __expf(-part));
            float p = r * s;
            tc += -fmaxf(logf(p), -100.f) + fmaxf(log1pf(-p), -100.f);
        }
    }
    if (lane == 0) g_rowAcc[b] += corr + tc;
}

// ---------------- tail GEMM + fused BCE ----------------
__global__ void __launch_bounds__(256) tail_kernel(const float* __restrict__ W2,
                                                   int hoff, int K, int osz, int cluster) {
    __shared__ __align__(16) __nv_bfloat16 smA[128 * 64];
    __shared__ __align__(16) __nv_bfloat16 smB[128 * 64];

    int nloc = blockIdx.x << 7;
    int nval = osz - nloc; if (nval > 128) nval = 128;
    int bm0 = blockIdx.y * 128;

    float c[2][8][4] = {};
    mma_loop(g_hb + hoff, K, bm0, W2, nloc, nval, K, smA, smB, c);

    int tid = threadIdx.x;
    int lane = tid & 31, wid = tid >> 5;
    int wm = wid & 3, wn = wid >> 2;
    float* sRow = reinterpret_cast<float*>(smA);
    if (tid < 128) sRow[tid] = 0.f;
    __syncthreads();

    #pragma unroll
    for (int tt = 0; tt < 2; ++tt) {
        int lr = wm * 32 + tt * 16 + (lane >> 2);
        float root0 = g_root[(bm0 + lr) * 3 + cluster];
        float root1 = g_root[(bm0 + lr + 8) * 3 + cluster];
        float rs0 = 0.f, rs1 = 0.f;
        #pragma unroll
        for (int n = 0; n < 8; ++n) {
            int col = wn * 64 + n * 8 + (lane & 3) * 2;
            #pragma unroll
            for (int q = 0; q < 2; ++q) {
                if (col + q < nval) {
                    float l0 = c[tt][n][q];
                    float l1 = c[tt][n][2 + q];
                    float p0 = __fdividef(root0, 1.f + __expf(-l0));
                    float p1 = __fdividef(root1, 1.f + __expf(-l1));
                    rs0 += -fmaxf(__logf(1.f - p0), -100.f);
                    rs1 += -fmaxf(__logf(1.f - p1), -100.f);
                }
            }
        }
        atomicAdd(&sRow[lr], rs0);
        atomicAdd(&sRow[lr + 8], rs1);
    }
    __syncthreads();
    if (tid < 128) {
        float act = g_active[(bm0 + tid) * 3 + cluster];
        if (act != 0.f) atomicAdd(&g_rowAcc[bm0 + tid], act * sRow[tid]);
    }
}

// ---------------- finalize ----------------
__global__ void finalize_kernel(float* __restrict__ out) {
    int tid = threadIdx.x;   // 256
    float v = g_rowAcc[tid] / g_num[tid];
    #pragma unroll
    for (int o = 16; o; o >>= 1) v += __shfl_xor_sync(0xffffffffu, v, o);
    __shared__ float sh[8];
    if ((tid & 31) == 0) sh[tid >> 5] = v;
    __syncthreads();
    if (tid == 0) {
        float s = 0.f;
        #pragma unroll
        for (int i = 0; i < 8; ++i) s += sh[i];
        out[0] = s / 256.f;
    }
}

// ---------------- launch ----------------
extern "C" void kernel_launch(void* const* d_in, const int* in_sizes, int n_in,
                              void* d_out, int out_size) {
    const float* x = nullptr;
    const float* headW = nullptr;
    const int* tgt = nullptr;
    const float* w1[3] = {nullptr, nullptr, nullptr};
    const float* w2[3] = {nullptr, nullptr, nullptr};
    const float* gb_a[3] = {nullptr, nullptr, nullptr};
    const float* gb_b[3] = {nullptr, nullptr, nullptr};
    int gbcount[3] = {0, 0, 0};

    for (int i = 0; i < n_in; ++i) {
        int s = in_sizes[i];
        const float* p = (const float*)d_in[i];
        switch (s) {
            case 196608:  x = p; break;
            case 1538304: headW = p; break;
            case 5120:    tgt = (const int*)d_in[i]; break;
            case 294912:  w1[0] = p; break;
            case 147456:  w1[1] = p; break;
            case 73728:   w1[2] = p; break;
            case 3840000: w2[0] = p; break;
            case 5376000: w2[1] = p; break;
            case 5760000: w2[2] = p; break;
            case 384: if (gbcount[0]++ == 0) gb_a[0] = p; else gb_b[0] = p; break;
            case 192: if (gbcount[1]++ == 0) gb_a[1] = p; else gb_b[1] = p; break;
            case 96:  if (gbcount[2]++ == 0) gb_a[2] = p; else gb_b[2] = p; break;
            default: break;
        }
    }

    prep_kernel<<<MROWS, 256>>>(x, tgt);
    mm1_kernel<<<dim3(22, 2), 256>>>(headW, w1[0], w1[1], w1[2]);
    ln_kernel<<<dim3(MROWS, 3), 128>>>(gb_a[0], gb_b[0], gb_a[1], gb_b[1], gb_a[2], gb_b[2]);
    fixup_kernel<<<MROWS, 32>>>(tgt, w2[0], w2[1], w2[2]);
    tail_kernel<<<dim3(79, 2),  256>>>(w2[0], 0,      384, 10000, 0);
    tail_kernel<<<dim3(219, 2), 256>>>(w2[1], 98304,  192, 28000, 1);
    tail_kernel<<<dim3(469, 2), 256>>>(w2[2], 147456, 96,  60000, 2);
    finalize_kernel<<<1, 256>>>((float*)d_out);
}

// round 5
// speedup vs baseline: 5.8975x; 1.5138x over previous
#include <cuda_runtime.h>
#include <cuda_bf16.h>
#include <math.h>
#include <stdint.h>

#define MROWS  256
#define INF_   768
#define SHORTN 2000
#define NHEAD  2003
#define LTGT   20

// clusters: lows 2000,12000,40000,100000; OSZ 10000,28000,60000; HSZ 384,192,96
// hidden pack offsets (elements): 0, 98304, 147456

// ---------------- device scratch ----------------
__device__ __align__(16) __nv_bfloat16 g_xb[MROWS * INF_];
__device__ __align__(16) float          g_h[MROWS * 672];
__device__ __align__(16) __nv_bfloat16 g_hb[MROWS * 672];
__device__ __align__(16) float          g_hl[MROWS * NHEAD];
__device__ float g_rowAcc[MROWS];
__device__ float g_num[MROWS];
__device__ float g_active[MROWS * 3];
__device__ float g_root[MROWS * 3];
__device__ int   g_uniq[MROWS * LTGT];

__device__ __forceinline__ uint32_t smem_u32(const void* p) {
    uint32_t a;
    asm("{ .reg .u64 t; cvta.to.shared.u64 t, %1; cvt.u32.u64 %0, t; }" : "=r"(a) : "l"(p));
    return a;
}

#define LDSM_X4(d0, d1, d2, d3, addr) \
    asm volatile("ldmatrix.sync.aligned.m8n8.x4.shared.b16 {%0,%1,%2,%3}, [%4];" \
        : "=r"(d0), "=r"(d1), "=r"(d2), "=r"(d3) : "r"(addr))

#define MMA16816(c, a, b) \
    asm volatile("mma.sync.aligned.m16n8k16.row.col.f32.bf16.bf16.f32 " \
        "{%0,%1,%2,%3},{%4,%5,%6,%7},{%8,%9},{%0,%1,%2,%3};" \
        : "+f"((c)[0]), "+f"((c)[1]), "+f"((c)[2]), "+f"((c)[3]) \
        : "r"((a)[0]), "r"((a)[1]), "r"((a)[2]), "r"((a)[3]), "r"((b)[0]), "r"((b)[1]))

// ---------------- warp-MMA mainloop ----------------
// c[2][8][4] += A[bm0:+128, 0:K](bf16, ldA) @ W[nloc:+nval, 0:K](fp32)^T
__device__ __forceinline__ void mma_loop(
    const __nv_bfloat16* __restrict__ A, int ldA, int bm0,
    const float* __restrict__ W, int nloc, int nval, int K,
    __nv_bfloat16* smA, __nv_bfloat16* smB, float c[2][8][4])
{
    int tid = threadIdx.x;
    int lane = tid & 31, wid = tid >> 5;
    int wm = wid & 3, wn = wid >> 2;
    int lo3 = lane & 7, gg1 = (lane >> 3) & 1, gg2 = (lane >> 4) & 1;
    uint32_t smAu = smem_u32(smA), smBu = smem_u32(smB);

    int nchunk = (K + 63) >> 6;
    for (int ch = 0; ch < nchunk; ++ch) {
        int kbase = ch << 6;
        int kreal = K - kbase; if (kreal > 64) kreal = 64;
        __syncthreads();

        #pragma unroll
        for (int it = 0; it < 4; ++it) {
            int idx = tid + it * 256;
            int r = idx >> 3, kc = idx & 7;
            if (kc * 8 < kreal) {
                uint4 v = *reinterpret_cast<const uint4*>(
                    A + (size_t)(bm0 + r) * ldA + kbase + kc * 8);
                *reinterpret_cast<uint4*>(
                    reinterpret_cast<char*>(smA) + r * 128 + ((kc ^ (r & 7)) << 4)) = v;
            }
        }
        #pragma unroll
        for (int it = 0; it < 4; ++it) {
            int idx = tid + it * 256;
            int r = idx >> 3, kc = idx & 7;
            if (kc * 8 < kreal) {
                uint4 o = make_uint4(0u, 0u, 0u, 0u);
                if (r < nval) {
                    const float* s = W + (size_t)(nloc + r) * K + kbase + kc * 8;
                    float4 v0 = *reinterpret_cast<const float4*>(s);
                    float4 v1 = *reinterpret_cast<const float4*>(s + 4);
                    asm("cvt.rn.bf16x2.f32 %0, %1, %2;" : "=r"(o.x) : "f"(v0.y), "f"(v0.x));
                    asm("cvt.rn.bf16x2.f32 %0, %1, %2;" : "=r"(o.y) : "f"(v0.w), "f"(v0.z));
                    asm("cvt.rn.bf16x2.f32 %0, %1, %2;" : "=r"(o.z) : "f"(v1.y), "f"(v1.x));
                    asm("cvt.rn.bf16x2.f32 %0, %1, %2;" : "=r"(o.w) : "f"(v1.w), "f"(v1.z));
                }
                *reinterpret_cast<uint4*>(
                    reinterpret_cast<char*>(smB) + r * 128 + ((kc ^ (r & 7)) << 4)) = o;
            }
        }
        __syncthreads();

        int ks = kreal >> 4;
        for (int s = 0; s < ks; ++s) {
            uint32_t a[2][4];
            #pragma unroll
            for (int t = 0; t < 2; ++t) {
                int row = wm * 32 + t * 16 + gg1 * 8 + lo3;
                uint32_t ad = smAu + row * 128 + (((2 * s + gg2) ^ (row & 7)) << 4);
                LDSM_X4(a[t][0], a[t][1], a[t][2], a[t][3], ad);
            }
            uint32_t b[8][2];
            #pragma unroll
            for (int p = 0; p < 4; ++p) {
                int row = wn * 64 + p * 16 + gg2 * 8 + lo3;
                uint32_t bd = smBu + row * 128 + (((2 * s + gg1) ^ (row & 7)) << 4);
                LDSM_X4(b[2 * p][0], b[2 * p][1], b[2 * p + 1][0], b[2 * p + 1][1], bd);
            }
            #pragma unroll
            for (int t = 0; t < 2; ++t)
                #pragma unroll
                for (int n = 0; n < 8; ++n)
                    MMA16816(c[t][n], a[t], b[n]);
        }
    }
    __syncthreads();
}

// ---------------- prep: x -> bf16, per-row init ----------------
__global__ void prep_kernel(const float* __restrict__ x, const int* __restrict__ tgt) {
    int b = blockIdx.x;
    int tid = threadIdx.x;
    for (int k = tid; k < INF_; k += 256)
        g_xb[b * INF_ + k] = __float2bfloat16(x[(size_t)b * INF_ + k]);

    if (tid < 32) {
        int lane = tid;
        int t = (lane < LTGT) ? tgt[b * LTGT + lane] : -1;
        int uniq = (lane < LTGT) ? 1 : 0;
        #pragma unroll
        for (int j = 0; j < LTGT; ++j) {
            int tj = __shfl_sync(0xffffffffu, t, j);
            if (j < lane && tj == t) uniq = 0;
        }
        if (lane < LTGT) g_uniq[b * LTGT + lane] = uniq;

        const int lows[4] = {2000, 12000, 40000, 100000};
        float num = (float)SHORTN;
        #pragma unroll
        for (int i = 0; i < 3; ++i) {
            bool in = (lane < LTGT) && (t >= lows[i]) && (t < lows[i + 1]);
            unsigned ball = __ballot_sync(0xffffffffu, in);
            float a = ball ? 1.f : 0.f;
            if (lane == 0) g_active[b * 3 + i] = a;
            num += (1.f - a) + a * (float)(lows[i + 1] - lows[i]);
        }
        if (lane == 0) { g_num[b] = num; g_rowAcc[b] = 0.f; }
    }
}

// ---------------- mm1: head + hidden GEMMs ----------------
__global__ void __launch_bounds__(256) mm1_kernel(const float* __restrict__ headW,
                                                  const float* __restrict__ w1_0,
                                                  const float* __restrict__ w1_1,
                                                  const float* __restrict__ w1_2) {
    __shared__ __align__(16) __nv_bfloat16 smA[128 * 64];
    __shared__ __align__(16) __nv_bfloat16 smB[128 * 64];

    int t = blockIdx.x;
    int bm0 = blockIdx.y * 128;
    const float* W; float* outF; int ldc, nloc, nval, mode;
    if (t < 16)      { W = headW; outF = g_hl;         ldc = NHEAD; nloc = t << 7;        nval = NHEAD - nloc; if (nval > 128) nval = 128; mode = 1; }
    else if (t < 19) { W = w1_0;  outF = g_h;          ldc = 384;   nloc = (t - 16) << 7; nval = 128; mode = 0; }
    else if (t < 21) { W = w1_1;  outF = g_h + 98304;  ldc = 192;   nloc = (t - 19) << 7; nval = 192 - nloc; if (nval > 128) nval = 128; mode = 0; }
    else             { W = w1_2;  outF = g_h + 147456; ldc = 96;    nloc = 0;             nval = 96;  mode = 0; }

    float c[2][8][4] = {};
    mma_loop(g_xb, INF_, bm0, W, nloc, nval, INF_, smA, smB, c);

    int tid = threadIdx.x;
    int lane = tid & 31, wid = tid >> 5;
    int wm = wid & 3, wn = wid >> 2;
    float* sRow = reinterpret_cast<float*>(smA);
    if (mode == 1) { if (tid < 128) sRow[tid] = 0.f; }
    __syncthreads();

    float rs[2][2] = {{0.f, 0.f}, {0.f, 0.f}};
    #pragma unroll
    for (int tt = 0; tt < 2; ++tt) {
        int r0 = bm0 + wm * 32 + tt * 16 + (lane >> 2);
        #pragma unroll
        for (int n = 0; n < 8; ++n) {
            int col = wn * 64 + n * 8 + (lane & 3) * 2;
            #pragma unroll
            for (int q = 0; q < 2; ++q) {
                if (col + q < nval) {
                    float l0 = c[tt][n][q];
                    float l1 = c[tt][n][2 + q];
                    outF[(size_t)r0 * ldc + nloc + col + q] = l0;
                    outF[(size_t)(r0 + 8) * ldc + nloc + col + q] = l1;
                    if (mode == 1) {
                        rs[tt][0] += fmaxf(l0, 0.f) + log1pf(__expf(-fabsf(l0)));
                        rs[tt][1] += fmaxf(l1, 0.f) + log1pf(__expf(-fabsf(l1)));
                    }
                }
            }
        }
    }
    if (mode == 1) {
        #pragma unroll
        for (int tt = 0; tt < 2; ++tt) {
            int lr = wm * 32 + tt * 16 + (lane >> 2);
            atomicAdd(&sRow[lr], rs[tt][0]);
            atomicAdd(&sRow[lr + 8], rs[tt][1]);
        }
        __syncthreads();
        if (tid < 128) atomicAdd(&g_rowAcc[bm0 + tid], sRow[tid]);
    }
}

// ---------------- LayerNorm + ReLU (fp32 + bf16 out) ----------------
__global__ void ln_kernel(const float* __restrict__ p1a, const float* __restrict__ p2a,
                          const float* __restrict__ p1b, const float* __restrict__ p2b,
                          const float* __restrict__ p1c, const float* __restrict__ p2c) {
    int ci = blockIdx.y;
    int b = blockIdx.x;
    int H, hoff; const float* p1; const float* p2;
    if (ci == 0)      { H = 384; hoff = 0;      p1 = p1a; p2 = p2a; }
    else if (ci == 1) { H = 192; hoff = 98304;  p1 = p1b; p2 = p2b; }
    else              { H = 96;  hoff = 147456; p1 = p1c; p2 = p2c; }
    float* row = g_h + hoff + (size_t)b * H;
    __nv_bfloat16* rowb = g_hb + hoff + (size_t)b * H;

    float v1 = p1[0], v2 = p2[0];
    const float* gp = (fabsf(v1 - 1.f) <= fabsf(v2 - 1.f)) ? p1 : p2;
    const float* bp = (gp == p1) ? p2 : p1;

    int tid = threadIdx.x;   // 128
    float s = 0.f, ss = 0.f;
    for (int k = tid; k < H; k += 128) {
        float v = row[k];
        s += v; ss += v * v;
    }
    #pragma unroll
    for (int o = 16; o; o >>= 1) {
        s  += __shfl_xor_sync(0xffffffffu, s, o);
        ss += __shfl_xor_sync(0xffffffffu, ss, o);
    }
    __shared__ float sh[10];
    int w = tid >> 5;
    if ((tid & 31) == 0) { sh[w] = s; sh[4 + w] = ss; }
    __syncthreads();
    if (tid == 0) {
        float S = sh[0] + sh[1] + sh[2] + sh[3];
        float SS = sh[4] + sh[5] + sh[6] + sh[7];
        sh[8] = S / (float)H;
        sh[9] = SS / (float)H;
    }
    __syncthreads();
    float mu = sh[8];
    float inv = rsqrtf(sh[9] - mu * mu + 1e-5f);
    for (int k = tid; k < H; k += 128) {
        float v = fmaxf((row[k] - mu) * inv * gp[k] + bp[k], 0.f);
        row[k] = v;
        rowb[k] = __float2bfloat16(v);
    }
}

// ---------------- fixup (parallel: 8 warps) ----------------
__global__ void __launch_bounds__(256) fixup_kernel(const int* __restrict__ tgt,
                             const float* __restrict__ w2_0,
                             const float* __restrict__ w2_1,
                             const float* __restrict__ w2_2) {
    int b = blockIdx.x;
    int tid = threadIdx.x;
    int lane = tid & 31, wid = tid >> 5;
    __shared__ float s_root[3];

    if (wid == 0) {
        int t  = (lane < LTGT) ? tgt[b * LTGT + lane] : -1;
        int uq = (lane < LTGT) ? g_uniq[b * LTGT + lane] : 0;
        float corr = 0.f;
        if (uq && t >= 0 && t < SHORTN) corr -= g_hl[b * NHEAD + t];
        if (lane < 3) {
            float l = g_hl[b * NHEAD + SHORTN + lane];
            float a = g_active[b * 3 + lane];
            corr += -a * (fmaxf(l, 0.f) + log1pf(__expf(-fabsf(l))));
            float r = 1.f / (1.f + __expf(-l));
            g_root[b * 3 + lane] = r;
            s_root[lane] = r;
        }
        #pragma unroll
        for (int o = 16; o; o >>= 1) corr += __shfl_xor_sync(0xffffffffu, corr, o);
        if (lane == 0) atomicAdd(&g_rowAcc[b], corr);
    }
    __syncthreads();

    float tc = 0.f;
    for (int j = wid; j < LTGT; j += 8) {
        int tj = tgt[b * LTGT + j];
        int uj = g_uniq[b * LTGT + j];
        if (!uj || tj < SHORTN) continue;
        const float* w2; int H, hoff, low, ci;
        if (tj < 12000)      { w2 = w2_0; H = 384; hoff = 0;      low = 2000;  ci = 0; }
        else if (tj < 40000) { w2 = w2_1; H = 192; hoff = 98304;  low = 12000; ci = 1; }
        else                 { w2 = w2_2; H = 96;  hoff = 147456; low = 40000; ci = 2; }
        int col = tj - low;
        const float* hrow = g_h + hoff + (size_t)b * H;
        const float* wrow = w2 + (size_t)col * H;
        float part = 0.f;
        for (int k = lane; k < H; k += 32) part += hrow[k] * wrow[k];
        #pragma unroll
        for (int o = 16; o; o >>= 1) part += __shfl_xor_sync(0xffffffffu, part, o);
        if (lane == 0) {
            float r = s_root[ci];
            float s = 1.f / (1.f + __expf(-part));
            float p = r * s;
            tc += -fmaxf(logf(p), -100.f) + fmaxf(log1pf(-p), -100.f);
        }
    }
    if (lane == 0 && tc != 0.f) atomicAdd(&g_rowAcc[b], tc);
}

// ---------------- fused tail GEMM + BCE (single launch) ----------------
__global__ void __launch_bounds__(256) tail_kernel(const float* __restrict__ w2_0,
                                                   const float* __restrict__ w2_1,
                                                   const float* __restrict__ w2_2) {
    __shared__ __align__(16) __nv_bfloat16 smA[128 * 64];
    __shared__ __align__(16) __nv_bfloat16 smB[128 * 64];

    int bx = blockIdx.x;
    const float* W2; int hoff, K, osz, cl, nb;
    if (bx < 79)       { W2 = w2_0; hoff = 0;      K = 384; osz = 10000; cl = 0; nb = bx; }
    else if (bx < 298) { W2 = w2_1; hoff = 98304;  K = 192; osz = 28000; cl = 1; nb = bx - 79; }
    else               { W2 = w2_2; hoff = 147456; K = 96;  osz = 60000; cl = 2; nb = bx - 298; }

    int nloc = nb << 7;
    int nval = osz - nloc; if (nval > 128) nval = 128;
    int bm0 = blockIdx.y * 128;

    float c[2][8][4] = {};
    mma_loop(g_hb + hoff, K, bm0, W2, nloc, nval, K, smA, smB, c);

    int tid = threadIdx.x;
    int lane = tid & 31, wid = tid >> 5;
    int wm = wid & 3, wn = wid >> 2;
    float* sRow = reinterpret_cast<float*>(smA);
    if (tid < 128) sRow[tid] = 0.f;
    __syncthreads();

    #pragma unroll
    for (int tt = 0; tt < 2; ++tt) {
        int lr = wm * 32 + tt * 16 + (lane >> 2);
        float root0 = g_root[(bm0 + lr) * 3 + cl];
        float root1 = g_root[(bm0 + lr + 8) * 3 + cl];
        float rs0 = 0.f, rs1 = 0.f;
        float pn0 = 1.f, pd0 = 1.f, pn1 = 1.f, pd1 = 1.f;
        #pragma unroll
        for (int n = 0; n < 8; ++n) {
            int col = wn * 64 + n * 8 + (lane & 3) * 2;
            #pragma unroll
            for (int q = 0; q < 2; ++q) {
                if (col + q < nval) {
                    float e0 = __expf(-c[tt][n][q]);
                    float e1 = __expf(-c[tt][n][2 + q]);
                    pn0 *= (1.f + e0 - root0); pd0 *= (1.f + e0);
                    pn1 *= (1.f + e1 - root1); pd1 *= (1.f + e1);
                }
            }
            if (n & 1) {   // flush every 4 elements/row
                rs0 += __logf(pd0) - __logf(pn0);
                rs1 += __logf(pd1) - __logf(pn1);
                pn0 = pd0 = pn1 = pd1 = 1.f;
            }
        }
        atomicAdd(&sRow[lr], rs0);
        atomicAdd(&sRow[lr + 8], rs1);
    }
    __syncthreads();
    if (tid < 128) {
        float act = g_active[(bm0 + tid) * 3 + cl];
        if (act != 0.f) atomicAdd(&g_rowAcc[bm0 + tid], act * sRow[tid]);
    }
}

// ---------------- finalize ----------------
__global__ void finalize_kernel(float* __restrict__ out) {
    int tid = threadIdx.x;   // 256
    float v = g_rowAcc[tid] / g_num[tid];
    #pragma unroll
    for (int o = 16; o; o >>= 1) v += __shfl_xor_sync(0xffffffffu, v, o);
    __shared__ float sh[8];
    if ((tid & 31) == 0) sh[tid >> 5] = v;
    __syncthreads();
    if (tid == 0) {
        float s = 0.f;
        #pragma unroll
        for (int i = 0; i < 8; ++i) s += sh[i];
        out[0] = s / 256.f;
    }
}

// ---------------- launch ----------------
extern "C" void kernel_launch(void* const* d_in, const int* in_sizes, int n_in,
                              void* d_out, int out_size) {
    const float* x = nullptr;
    const float* headW = nullptr;
    const int* tgt = nullptr;
    const float* w1[3] = {nullptr, nullptr, nullptr};
    const float* w2[3] = {nullptr, nullptr, nullptr};
    const float* gb_a[3] = {nullptr, nullptr, nullptr};
    const float* gb_b[3] = {nullptr, nullptr, nullptr};
    int gbcount[3] = {0, 0, 0};

    for (int i = 0; i < n_in; ++i) {
        int s = in_sizes[i];
        const float* p = (const float*)d_in[i];
        switch (s) {
            case 196608:  x = p; break;
            case 1538304: headW = p; break;
            case 5120:    tgt = (const int*)d_in[i]; break;
            case 294912:  w1[0] = p; break;
            case 147456:  w1[1] = p; break;
            case 73728:   w1[2] = p; break;
            case 3840000: w2[0] = p; break;
            case 5376000: w2[1] = p; break;
            case 5760000: w2[2] = p; break;
            case 384: if (gbcount[0]++ == 0) gb_a[0] = p; else gb_b[0] = p; break;
            case 192: if (gbcount[1]++ == 0) gb_a[1] = p; else gb_b[1] = p; break;
            case 96:  if (gbcount[2]++ == 0) gb_a[2] = p; else gb_b[2] = p; break;
            default: break;
        }
    }

    prep_kernel<<<MROWS, 256>>>(x, tgt);
    mm1_kernel<<<dim3(22, 2), 256>>>(headW, w1[0], w1[1], w1[2]);
    ln_kernel<<<dim3(MROWS, 3), 128>>>(gb_a[0], gb_b[0], gb_a[1], gb_b[1], gb_a[2], gb_b[2]);
    fixup_kernel<<<MROWS, 256>>>(tgt, w2[0], w2[1], w2[2]);
    tail_kernel<<<dim3(767, 2), 256>>>(w2[0], w2[1], w2[2]);
    finalize_kernel<<<1, 256>>>((float*)d_out);
}